// round 16
// baseline (speedup 1.0000x reference)
#include <cuda_runtime.h>
#include <cuda_fp16.h>
#include <stdint.h>

// Effective computation (GNN stack is dead code in the reference):
//   z   = x[samples[:,0]] * x[samples[:,1]]          [S, 256]
//   z   = relu(z @ lin1_W + lin1_b)                  [S, 256]
//   out = z @ lin2_W + lin2_b                        [S, 2]
//
// R15: fp16 mma.sync (m16n8k16, f32 accum). Per-chunk-overhead model
// (OV ~ 155 MMA-slots per sync) says: fewer, bigger chunks. KC=64, NCH=4,
// 256 threads / 8 warps, warp tile 64x64 (acc=128 regs, fits 255 budget —
// the reg-safe version of R11). 128 MMAs per warp between syncs.
// B fragments LDG-rotated one kk-step ahead; A gather prefetched one chunk
// ahead, packed+stored after kk0. A smem 144B stride, conflict-free.

#define KD  256
#define BM  128
#define KC  64
#define NCH 4

#define ABUF  18432              // per-buffer A: 128 rows x 144B
#define DSMEM (2 * ABUF)         // 36864

// W1 fp16 fragments: [kk_global 16][ntile 32][lane 32] -> uint2 {b0, b1}
__device__ uint2 g_Wf[16 * 32 * 32];

__device__ __forceinline__ uint32_t pack_f16x2(float lo, float hi) {
    uint32_t r;   // low 16 <- lo
    asm("cvt.rn.f16x2.f32 %0, %1, %2;" : "=r"(r) : "f"(hi), "f"(lo));
    return r;
}

__global__ void conv_w_kernel(const float* __restrict__ W1) {
    const int idx  = blockIdx.x * 256 + threadIdx.x;   // 16384 total
    const int lane = idx & 31;
    const int tile = (idx >> 5) & 31;
    const int kkg  = idx >> 10;                        // 0..15
    const int n  = tile * 8 + (lane >> 2);
    const int k0 = kkg * 16 + (lane & 3) * 2;
    const float w00 = W1[(size_t)k0 * KD + n];
    const float w01 = W1[(size_t)(k0 + 1) * KD + n];
    const float w10 = W1[(size_t)(k0 + 8) * KD + n];
    const float w11 = W1[(size_t)(k0 + 9) * KD + n];
    g_Wf[idx] = make_uint2(pack_f16x2(w00, w01), pack_f16x2(w10, w11));
}

__device__ __forceinline__ uint32_t smem_u32(const void* p) {
    uint32_t a;
    asm("{ .reg .u64 t; cvta.to.shared.u64 t, %1; cvt.u32.u64 %0, t; }"
        : "=r"(a) : "l"(p));
    return a;
}

#define LDSM4(r, addr) \
    asm volatile("ldmatrix.sync.aligned.m8n8.x4.shared.b16 {%0,%1,%2,%3}, [%4];" \
        : "=r"((r)[0]), "=r"((r)[1]), "=r"((r)[2]), "=r"((r)[3]) : "r"(addr))

#define MMA_F16(c, a, b0, b1) \
    asm volatile("mma.sync.aligned.m16n8k16.row.col.f32.f16.f16.f32 " \
        "{%0,%1,%2,%3}, {%4,%5,%6,%7}, {%8,%9}, {%0,%1,%2,%3};" \
        : "+f"((c)[0]), "+f"((c)[1]), "+f"((c)[2]), "+f"((c)[3]) \
        : "r"((a)[0]), "r"((a)[1]), "r"((a)[2]), "r"((a)[3]), "r"(b0), "r"(b1))

#define LOAD_WB(wB, kkg) do { \
    const uint2* _p = g_Wf + (kkg) * 1024 + nw * 256 + lane; \
    _Pragma("unroll") \
    for (int tn = 0; tn < 8; ++tn) (wB)[tn] = _p[tn * 32]; \
    } while (0)

// one kk-step: LDSM A for 4 m16 tiles (16 rows x 144B apart), 32 MMAs
#define KK_STEP(aAddr, wB) do { \
    uint32_t a[4][4]; \
    LDSM4(a[0], (aAddr)); \
    LDSM4(a[1], (aAddr) + 2304); \
    LDSM4(a[2], (aAddr) + 4608); \
    LDSM4(a[3], (aAddr) + 6912); \
    _Pragma("unroll") \
    for (int tn = 0; tn < 8; ++tn) { \
        _Pragma("unroll") \
        for (int tm = 0; tm < 4; ++tm) \
            MMA_F16(acc[tm][tn], a[tm], (wB)[tn].x, (wB)[tn].y); \
    } } while (0)

// pack 8 float4-pairs (32 k's) -> 4 uint4 and store at dst+stsOff
#define PACK_STS(dst, va, vb) do { \
    _Pragma("unroll") \
    for (int g = 0; g < 4; ++g) { \
        uint4 h; \
        h.x = pack_f16x2((va)[2*g].x * (vb)[2*g].x,   (va)[2*g].y * (vb)[2*g].y); \
        h.y = pack_f16x2((va)[2*g].z * (vb)[2*g].z,   (va)[2*g].w * (vb)[2*g].w); \
        h.z = pack_f16x2((va)[2*g+1].x * (vb)[2*g+1].x, (va)[2*g+1].y * (vb)[2*g+1].y); \
        h.w = pack_f16x2((va)[2*g+1].z * (vb)[2*g+1].z, (va)[2*g+1].w * (vb)[2*g+1].w); \
        *(uint4*)((dst) + stsOff + g * 16) = h; \
    } } while (0)

__global__ __launch_bounds__(256, 1) void fused_pair_mlp_mma(
    const float* __restrict__ x,
    const void*  __restrict__ samples_raw,
    const float* __restrict__ b1,
    const float* __restrict__ W2,
    const float* __restrict__ b2,
    float* __restrict__ out,
    int S, int n_nodes)
{
    extern __shared__ __align__(16) char dsm[];     // A buffers (fp16)
    __shared__ float  sb1[256];
    __shared__ float2 sw2[256];
    __shared__ float2 red[BM * 4];

    const uint32_t sb = smem_u32(dsm);
    const int tid  = threadIdx.x;
    const int lane = tid & 31;
    const int wid  = tid >> 5;
    const int mw   = wid >> 2;      // 0..1 (M 2x64)
    const int nw   = wid & 3;       // 0..3 (N 4x64)
    const int m0   = blockIdx.x * BM;

    sb1[tid] = b1[tid];
    sw2[tid] = *(const float2*)&W2[tid * 2];

    // ---- dtype detection: int64 vs int32 sample indices (uniform)
    const long long* s64 = (const long long*)samples_raw;
    const int*       s32 = (const int*)samples_raw;
    bool is64 = true;
#pragma unroll
    for (int i = 0; i < 4; ++i) {
        long long v = __ldg(&s64[i]);
        if (v < 0 || v >= (long long)n_nodes) is64 = false;
    }

    // ---- A staging map: thread t -> row t>>1 (0..127), 32 k's at (t&1)*32
    const int arow = tid >> 1;
    const int half = tid & 1;
    int gr = m0 + arow; if (gr >= S) gr = S - 1;
    long long ia, ib;
    if (is64) { ia = s64[(long long)gr * 2]; ib = s64[(long long)gr * 2 + 1]; }
    else      { ia = s32[gr * 2];            ib = s32[gr * 2 + 1]; }
    const float* xa = x + ia * KD + half * 32;
    const float* xb = x + ib * KD + half * 32;
    const uint32_t stsOff = (uint32_t)(arow * 144 + half * 64); // 32 fp16 = 64B

    // ---- ldmatrix A per-lane base (row-major m16 tiles, 144B row stride)
    const uint32_t aLane =
        2u * ((mw * 64 + (lane & 15)) * 72 + ((lane >> 4) << 3));

    float acc[4][8][4];
#pragma unroll
    for (int i = 0; i < 4; ++i)
#pragma unroll
        for (int j = 0; j < 8; ++j)
#pragma unroll
            for (int p = 0; p < 4; ++p) acc[i][j][p] = 0.f;

    uint2 wBa[8], wBb[8];

    // ---- prologue: stage chunk 0 (32 k's/thread) + prefetch B kkg=0
    {
        float4 va[8], vb[8];
#pragma unroll
        for (int j = 0; j < 8; ++j) {
            va[j] = *(const float4*)(xa + j * 4);
            vb[j] = *(const float4*)(xb + j * 4);
        }
        PACK_STS(dsm, va, vb);
    }
    LOAD_WB(wBa, 0);
    __syncthreads();

    // ---- K loop: 4 chunks of 64 (4 kk-steps each)
#pragma unroll 1
    for (int c = 0; c < NCH; ++c) {
        const int buf = c & 1;
        const uint32_t aBase = sb + buf * ABUF + aLane;
        const bool more = (c + 1 < NCH);
        const int kg = c * 4;

        // next chunk's gather loads (issued at chunk top; packed after kk0)
        float4 va[8], vb[8];
        if (more) {
            const int o = (c + 1) * KC;
#pragma unroll
            for (int j = 0; j < 8; ++j) {
                va[j] = *(const float4*)(xa + o + j * 4);
                vb[j] = *(const float4*)(xb + o + j * 4);
            }
        }

        // kk0 (wBa) | prefetch wBb = kg+1
        LOAD_WB(wBb, kg + 1);
        KK_STEP(aBase, wBa);

        // pack + store next chunk's A (LDG has ~1 kk-step of cover)
        if (more) {
            char* db = dsm + (buf ^ 1) * ABUF;
            PACK_STS(db, va, vb);
        }

        // kk1 (wBb) | prefetch wBa = kg+2
        LOAD_WB(wBa, kg + 2);
        KK_STEP(aBase + 32, wBb);

        // kk2 (wBa) | prefetch wBb = kg+3
        LOAD_WB(wBb, kg + 3);
        KK_STEP(aBase + 64, wBa);

        // kk3 (wBb) | prefetch wBa = kg+4 (next chunk's kk0)
        if (more) LOAD_WB(wBa, kg + 4);
        KK_STEP(aBase + 96, wBb);

        if (more) __syncthreads();
    }

    // ---- epilogue: bias + relu + [256,2] GEMM, warp-reduce then smem combine
    const int lr = lane >> 2;
    const int lc = (lane & 3) * 2;
#pragma unroll
    for (int tm = 0; tm < 4; ++tm) {
#pragma unroll
        for (int hh = 0; hh < 2; ++hh) {
            const int row = mw * 64 + tm * 16 + lr + hh * 8;
            float o0 = 0.f, o1 = 0.f;
#pragma unroll
            for (int tn = 0; tn < 8; ++tn) {
                const int cb = nw * 64 + tn * 8 + lc;
                const float z0 = fmaxf(acc[tm][tn][hh * 2 + 0] + sb1[cb], 0.f);
                const float z1 = fmaxf(acc[tm][tn][hh * 2 + 1] + sb1[cb + 1], 0.f);
                const float2 w0 = sw2[cb];
                const float2 w1 = sw2[cb + 1];
                o0 = fmaf(z0, w0.x, fmaf(z1, w1.x, o0));
                o1 = fmaf(z0, w0.y, fmaf(z1, w1.y, o1));
            }
            o0 += __shfl_xor_sync(0xffffffffu, o0, 1);
            o0 += __shfl_xor_sync(0xffffffffu, o0, 2);
            o1 += __shfl_xor_sync(0xffffffffu, o1, 1);
            o1 += __shfl_xor_sync(0xffffffffu, o1, 2);
            if ((lane & 3) == 0) red[row * 4 + nw] = make_float2(o0, o1);
        }
    }
    __syncthreads();

    if (tid < BM) {
        const int m = m0 + tid;
        if (m < S) {
            float2 s = red[tid * 4];
#pragma unroll
            for (int p = 1; p < 4; ++p) {
                s.x += red[tid * 4 + p].x;
                s.y += red[tid * 4 + p].y;
            }
            float2 o;
            o.x = s.x + b2[0];
            o.y = s.y + b2[1];
            *(float2*)(out + m * 2) = o;
        }
    }
}

extern "C" void kernel_launch(void* const* d_in, const int* in_sizes, int n_in,
                              void* d_out, int out_size) {
    // metadata order: x_feature, edge_index, samples, W1, b1, W2, b2,
    //                 lin1_W, lin1_b, lin2_W, lin2_b
    const float* x       = (const float*)d_in[0];
    const void*  samples = d_in[2];
    const float* lin1_W  = (const float*)d_in[7];
    const float* lin1_b  = (const float*)d_in[8];
    const float* lin2_W  = (const float*)d_in[9];
    const float* lin2_b  = (const float*)d_in[10];
    float* out = (float*)d_out;

    const int S       = in_sizes[2] / 2;
    const int n_nodes = in_sizes[0] / KD;
    const int grid    = (S + BM - 1) / BM;

    conv_w_kernel<<<64, 256>>>(lin1_W);

    cudaFuncSetAttribute(fused_pair_mlp_mma,
                         cudaFuncAttributeMaxDynamicSharedMemorySize, DSMEM);
    fused_pair_mlp_mma<<<grid, 256, DSMEM>>>(
        x, samples, lin1_b, lin2_W, lin2_b, out, S, n_nodes);
}

// round 17
// speedup vs baseline: 1.6448x; 1.6448x over previous
#include <cuda_runtime.h>
#include <cuda_fp16.h>
#include <stdint.h>

// Effective computation (GNN stack is dead code in the reference):
//   z   = x[samples[:,0]] * x[samples[:,1]]          [S, 256]
//   z   = relu(z @ lin1_W + lin1_b)                  [S, 256]
//   out = z @ lin2_W + lin2_b                        [S, 2]
//
// R16 = R7 verbatim (best measured: 66.1 us). Single-term fp16 mma.sync
// (m16n8k16, f32 accum); fp16 rounding of z and W gives ~2.8e-4 rel error
// (threshold 1e-3). 512 threads / 16 warps (4m x 4n), warp tile 32x64,
// CTA 128x256, pre-packed B fragments (direct LDG), double-buffered A smem.
// R8-R15 perturbations (occupancy, cp.async, chunk size, B residency) all
// regressed; this configuration is the empirical local optimum.

#define KD  256
#define BM  128
#define KC  32
#define NCH 8

#define ABUF  10240              // per-buffer A: 128 rows x 80B
#define DSMEM (2 * ABUF)         // 20480

// W1 fp16 fragments: [kk_global 16][ntile 32][lane 32] -> uint2 {b0, b1}
__device__ uint2 g_Wf[16 * 32 * 32];

__device__ __forceinline__ uint32_t pack_f16x2(float lo, float hi) {
    uint32_t r;   // low 16 <- lo
    asm("cvt.rn.f16x2.f32 %0, %1, %2;" : "=r"(r) : "f"(hi), "f"(lo));
    return r;
}

__global__ void conv_w_kernel(const float* __restrict__ W1) {
    const int idx  = blockIdx.x * 256 + threadIdx.x;   // 16384 total
    const int lane = idx & 31;
    const int tile = (idx >> 5) & 31;
    const int kkg  = idx >> 10;                        // 0..15
    const int n  = tile * 8 + (lane >> 2);
    const int k0 = kkg * 16 + (lane & 3) * 2;
    const float w00 = W1[(size_t)k0 * KD + n];
    const float w01 = W1[(size_t)(k0 + 1) * KD + n];
    const float w10 = W1[(size_t)(k0 + 8) * KD + n];
    const float w11 = W1[(size_t)(k0 + 9) * KD + n];
    g_Wf[idx] = make_uint2(pack_f16x2(w00, w01), pack_f16x2(w10, w11));
}

__device__ __forceinline__ uint32_t smem_u32(const void* p) {
    uint32_t a;
    asm("{ .reg .u64 t; cvta.to.shared.u64 t, %1; cvt.u32.u64 %0, t; }"
        : "=r"(a) : "l"(p));
    return a;
}

#define LDSM4(r, addr) \
    asm volatile("ldmatrix.sync.aligned.m8n8.x4.shared.b16 {%0,%1,%2,%3}, [%4];" \
        : "=r"((r)[0]), "=r"((r)[1]), "=r"((r)[2]), "=r"((r)[3]) : "r"(addr))

#define MMA_F16(c, a, b0, b1) \
    asm volatile("mma.sync.aligned.m16n8k16.row.col.f32.f16.f16.f32 " \
        "{%0,%1,%2,%3}, {%4,%5,%6,%7}, {%8,%9}, {%0,%1,%2,%3};" \
        : "+f"((c)[0]), "+f"((c)[1]), "+f"((c)[2]), "+f"((c)[3]) \
        : "r"((a)[0]), "r"((a)[1]), "r"((a)[2]), "r"((a)[3]), "r"(b0), "r"(b1))

__global__ __launch_bounds__(512, 1) void fused_pair_mlp_mma(
    const float* __restrict__ x,
    const void*  __restrict__ samples_raw,
    const float* __restrict__ b1,
    const float* __restrict__ W2,
    const float* __restrict__ b2,
    float* __restrict__ out,
    int S, int n_nodes)
{
    extern __shared__ __align__(16) char dsm[];     // A buffers (fp16)
    __shared__ float  sb1[256];
    __shared__ float2 sw2[256];
    __shared__ float2 red[BM * 4];

    const uint32_t sb = smem_u32(dsm);
    const int tid  = threadIdx.x;
    const int lane = tid & 31;
    const int wid  = tid >> 5;
    const int mw   = wid >> 2;      // 0..3 (M 4x32)
    const int nw   = wid & 3;       // 0..3 (N 4x64)
    const int m0   = blockIdx.x * BM;

    if (tid < 256) {
        sb1[tid] = b1[tid];
        sw2[tid] = *(const float2*)&W2[tid * 2];
    }

    // ---- dtype detection: int64 vs int32 sample indices (uniform)
    const long long* s64 = (const long long*)samples_raw;
    const int*       s32 = (const int*)samples_raw;
    bool is64 = true;
#pragma unroll
    for (int i = 0; i < 4; ++i) {
        long long v = __ldg(&s64[i]);
        if (v < 0 || v >= (long long)n_nodes) is64 = false;
    }

    // ---- A staging map: thread t -> row t>>2 (0..127), 8 k's at (t&3)*8
    const int arow = tid >> 2;
    const int q    = tid & 3;
    int gr = m0 + arow; if (gr >= S) gr = S - 1;
    long long ia, ib;
    if (is64) { ia = s64[(long long)gr * 2]; ib = s64[(long long)gr * 2 + 1]; }
    else      { ia = s32[gr * 2];            ib = s32[gr * 2 + 1]; }
    const float* xa = x + ia * KD + q * 8;
    const float* xb = x + ib * KD + q * 8;
    const uint32_t stsOff = (uint32_t)(arow * 80 + q * 16);  // 8 fp16 = 16B

    // ---- ldmatrix A per-lane base (row-major m16 tiles, 80B row stride)
    const uint32_t aLane =
        2u * ((mw * 32 + (lane & 15)) * 40 + ((lane >> 4) << 3));

    float acc[2][8][4];
#pragma unroll
    for (int i = 0; i < 2; ++i)
#pragma unroll
        for (int j = 0; j < 8; ++j)
#pragma unroll
            for (int p = 0; p < 4; ++p) acc[i][j][p] = 0.f;

    // ---- prologue: stage chunk 0 into buffer 0 (8 products -> 8 fp16 = 16B)
    {
        const float4 va0 = *(const float4*)xa;
        const float4 va1 = *(const float4*)(xa + 4);
        const float4 vb0 = *(const float4*)xb;
        const float4 vb1 = *(const float4*)(xb + 4);
        uint4 h;
        h.x = pack_f16x2(va0.x * vb0.x, va0.y * vb0.y);
        h.y = pack_f16x2(va0.z * vb0.z, va0.w * vb0.w);
        h.z = pack_f16x2(va1.x * vb1.x, va1.y * vb1.y);
        h.w = pack_f16x2(va1.z * vb1.z, va1.w * vb1.w);
        *(uint4*)(dsm + stsOff) = h;
    }
    __syncthreads();

    // ---- K loop: 8 chunks of 32
#pragma unroll 1
    for (int c = 0; c < NCH; ++c) {
        const int buf = c & 1;
        const uint32_t aBase = sb + buf * ABUF + aLane;
        const bool more = (c + 1 < NCH);

        // next chunk's gather loads (latency hidden under kk0 MMAs)
        float4 va0, va1, vb0, vb1;
        if (more) {
            const int k0n = (c + 1) * KC;
            va0 = *(const float4*)(xa + k0n);
            va1 = *(const float4*)(xa + k0n + 4);
            vb0 = *(const float4*)(xb + k0n);
            vb1 = *(const float4*)(xb + k0n + 4);
        }

        // ---- kk = 0
        {
            uint32_t a0[4], a1[4];
            LDSM4(a0, aBase);
            LDSM4(a1, aBase + 1280);
            const uint2* pB = g_Wf + (c * 2) * 1024 + nw * 256 + lane;
            uint2 wB[8];
#pragma unroll
            for (int tn = 0; tn < 8; ++tn) wB[tn] = pB[tn * 32];
#pragma unroll
            for (int tn = 0; tn < 8; ++tn) {
                MMA_F16(acc[0][tn], a0, wB[tn].x, wB[tn].y);
                MMA_F16(acc[1][tn], a1, wB[tn].x, wB[tn].y);
            }
        }

        // stage next chunk into the other buffer (overlaps kk0 MMA drain)
        if (more) {
            uint4 h;
            h.x = pack_f16x2(va0.x * vb0.x, va0.y * vb0.y);
            h.y = pack_f16x2(va0.z * vb0.z, va0.w * vb0.w);
            h.z = pack_f16x2(va1.x * vb1.x, va1.y * vb1.y);
            h.w = pack_f16x2(va1.z * vb1.z, va1.w * vb1.w);
            *(uint4*)(dsm + (buf ^ 1) * ABUF + stsOff) = h;
        }

        // ---- kk = 1
        {
            uint32_t a0[4], a1[4];
            LDSM4(a0, aBase + 32);
            LDSM4(a1, aBase + 1280 + 32);
            const uint2* pB = g_Wf + (c * 2 + 1) * 1024 + nw * 256 + lane;
            uint2 wB[8];
#pragma unroll
            for (int tn = 0; tn < 8; ++tn) wB[tn] = pB[tn * 32];
#pragma unroll
            for (int tn = 0; tn < 8; ++tn) {
                MMA_F16(acc[0][tn], a0, wB[tn].x, wB[tn].y);
                MMA_F16(acc[1][tn], a1, wB[tn].x, wB[tn].y);
            }
        }

        if (more) __syncthreads();
    }

    // ---- epilogue: bias + relu + [256,2] GEMM, warp-reduce then smem combine
    const int lr = lane >> 2;
    const int lc = (lane & 3) * 2;
#pragma unroll
    for (int tm = 0; tm < 2; ++tm) {
#pragma unroll
        for (int hh = 0; hh < 2; ++hh) {
            const int row = mw * 32 + tm * 16 + lr + hh * 8;
            float o0 = 0.f, o1 = 0.f;
#pragma unroll
            for (int tn = 0; tn < 8; ++tn) {
                const int cb = nw * 64 + tn * 8 + lc;
                const float z0 = fmaxf(acc[tm][tn][hh * 2 + 0] + sb1[cb], 0.f);
                const float z1 = fmaxf(acc[tm][tn][hh * 2 + 1] + sb1[cb + 1], 0.f);
                const float2 w0 = sw2[cb];
                const float2 w1 = sw2[cb + 1];
                o0 = fmaf(z0, w0.x, fmaf(z1, w1.x, o0));
                o1 = fmaf(z0, w0.y, fmaf(z1, w1.y, o1));
            }
            o0 += __shfl_xor_sync(0xffffffffu, o0, 1);
            o0 += __shfl_xor_sync(0xffffffffu, o0, 2);
            o1 += __shfl_xor_sync(0xffffffffu, o1, 1);
            o1 += __shfl_xor_sync(0xffffffffu, o1, 2);
            if ((lane & 3) == 0) red[row * 4 + nw] = make_float2(o0, o1);
        }
    }
    __syncthreads();

    if (tid < BM) {
        const int m = m0 + tid;
        if (m < S) {
            float2 s = red[tid * 4];
#pragma unroll
            for (int p = 1; p < 4; ++p) {
                s.x += red[tid * 4 + p].x;
                s.y += red[tid * 4 + p].y;
            }
            float2 o;
            o.x = s.x + b2[0];
            o.y = s.y + b2[1];
            *(float2*)(out + m * 2) = o;
        }
    }
}

extern "C" void kernel_launch(void* const* d_in, const int* in_sizes, int n_in,
                              void* d_out, int out_size) {
    // metadata order: x_feature, edge_index, samples, W1, b1, W2, b2,
    //                 lin1_W, lin1_b, lin2_W, lin2_b
    const float* x       = (const float*)d_in[0];
    const void*  samples = d_in[2];
    const float* lin1_W  = (const float*)d_in[7];
    const float* lin1_b  = (const float*)d_in[8];
    const float* lin2_W  = (const float*)d_in[9];
    const float* lin2_b  = (const float*)d_in[10];
    float* out = (float*)d_out;

    const int S       = in_sizes[2] / 2;
    const int n_nodes = in_sizes[0] / KD;
    const int grid    = (S + BM - 1) / BM;

    conv_w_kernel<<<64, 256>>>(lin1_W);

    cudaFuncSetAttribute(fused_pair_mlp_mma,
                         cudaFuncAttributeMaxDynamicSharedMemorySize, DSMEM);
    fused_pair_mlp_mma<<<grid, 512, DSMEM>>>(
        x, samples, lin1_b, lin2_W, lin2_b, out, S, n_nodes);
}